// round 12
// baseline (speedup 1.0000x reference)
#include <cuda_runtime.h>
#include <cuda_bf16.h>
#include <cstdint>

#define BATCH 4
#define SEQ   2048
#define DM    1024
#define TOKENS (BATCH * SEQ)   // 8192

#define BM 128
#define BN 256
#define BKH 32                           // K per stage (bf16 elements)
#define NTHREADS 256
#define TILE_A  (BM * BKH * 2)           // 8192 B  (Ah or Al)
#define TILE_BB (BN * BKH * 2)           // 16384 B (Bh or Bl)
#define STAGE_B (2 * TILE_A + 2 * TILE_BB) // 49152
#define SMEM_TOTAL (4 * STAGE_B)         // 196608 (4 stages)

// ---------------------------------------------------------------------------
// Scratch (__device__ globals; 16B-aligned)
// ---------------------------------------------------------------------------
__device__ __align__(16) __nv_bfloat16 g_xh[(size_t)TOKENS * DM];
__device__ __align__(16) __nv_bfloat16 g_xl[(size_t)TOKENS * DM];
__device__ __align__(16) __nv_bfloat16 g_wth[3][(size_t)DM * DM];  // W^T [n][k]
__device__ __align__(16) __nv_bfloat16 g_wtl[3][(size_t)DM * DM];
__device__ __align__(16) __nv_bfloat16 g_qh[(size_t)TOKENS * DM];
__device__ __align__(16) __nv_bfloat16 g_ql[(size_t)TOKENS * DM];
__device__ __align__(16) __nv_bfloat16 g_kh[(size_t)TOKENS * DM];
__device__ __align__(16) __nv_bfloat16 g_kl[(size_t)TOKENS * DM];
__device__ __align__(16) __nv_bfloat16 g_vth[(size_t)BATCH * DM * SEQ]; // V^T [e][n]
__device__ __align__(16) __nv_bfloat16 g_vtl[(size_t)BATCH * DM * SEQ];
__device__ __align__(16) float         g_s [(size_t)BATCH * SEQ * SEQ];
__device__ __align__(16) __nv_bfloat16 g_ph[(size_t)BATCH * SEQ * SEQ];
__device__ __align__(16) __nv_bfloat16 g_pl[(size_t)BATCH * SEQ * SEQ];

// ---------------------------------------------------------------------------
// PTX helpers — baseline ISA only (compiles under compute_103)
// ---------------------------------------------------------------------------
__device__ __forceinline__ uint32_t smem_u32(const void* p) {
    uint32_t a;
    asm("{ .reg .u64 t; cvta.to.shared.u64 t, %1; cvt.u32.u64 %0, t; }"
        : "=r"(a) : "l"(p));
    return a;
}

#define CP16(dst, src) \
    asm volatile("cp.async.cg.shared.global [%0], [%1], 16;" \
        :: "r"(dst), "l"(src) : "memory")
#define CP_COMMIT() asm volatile("cp.async.commit_group;" ::: "memory")
#define CP_WAIT(N)  asm volatile("cp.async.wait_group %0;" :: "n"(N) : "memory")

__device__ __forceinline__ void ldm4(uint32_t* r, uint32_t addr) {
    asm volatile("ldmatrix.sync.aligned.m8n8.x4.shared.b16 {%0,%1,%2,%3}, [%4];"
        : "=r"(r[0]), "=r"(r[1]), "=r"(r[2]), "=r"(r[3]) : "r"(addr));
}

__device__ __forceinline__ void mma16(float* d, const uint32_t* a, const uint32_t* b) {
    asm volatile(
        "mma.sync.aligned.m16n8k16.row.col.f32.bf16.bf16.f32 "
        "{%0,%1,%2,%3}, {%4,%5,%6,%7}, {%8,%9}, {%0,%1,%2,%3};"
        : "+f"(d[0]), "+f"(d[1]), "+f"(d[2]), "+f"(d[3])
        : "r"(a[0]), "r"(a[1]), "r"(a[2]), "r"(a[3]), "r"(b[0]), "r"(b[1]));
}

// Tile of R rows x 32 bf16 stored as (R/2) rows x 128B with SW128 swizzle.
// Logical (r, c16) with c16 in [0,4): prow = r % (R/2), chunk = c16 + 4*(r/(R/2)).
// off = prow*128 + ((chunk ^ (prow&7)) * 16). hshift = log2(R/2).
__device__ __forceinline__ uint32_t toff(uint32_t r, uint32_t c, uint32_t hshift) {
    const uint32_t prow  = r & ((1u << hshift) - 1u);
    const uint32_t chunk = c + ((r >> hshift) << 2);
    return prow * 128u + ((chunk ^ (prow & 7u)) * 16u);
}

// ---------------------------------------------------------------------------
// Stage load (256 threads): Ah,Al 128x32 (2 cp16/thr each), Bh,Bl 256x32 (4 each)
// ---------------------------------------------------------------------------
__device__ __forceinline__ void stage_load(
    uint32_t sbase,
    const __nv_bfloat16* __restrict__ Ah, const __nv_bfloat16* __restrict__ Al,
    long lda, long m0,
    const __nv_bfloat16* __restrict__ Bh, const __nv_bfloat16* __restrict__ Bl,
    long ldb, long n0,
    long k0, int tid)
{
    // A tiles: row = tid>>1, chunks (tid&1)*2 + {0,1}
    const uint32_t ra = (uint32_t)(tid >> 1);
    const uint32_t ca = (uint32_t)((tid & 1) * 2);
    const __nv_bfloat16* a0 = Ah + (m0 + ra) * lda + k0;
    const __nv_bfloat16* a1 = Al + (m0 + ra) * lda + k0;
#pragma unroll
    for (int i = 0; i < 2; i++) {
        const uint32_t c = ca + i;
        const uint32_t d = toff(ra, c, 6);
        CP16(sbase + d,          a0 + c * 8);
        CP16(sbase + TILE_A + d, a1 + c * 8);
    }
    // B tiles: row = tid, chunks 0..3
    const __nv_bfloat16* b0 = Bh + (n0 + tid) * ldb + k0;
    const __nv_bfloat16* b1 = Bl + (n0 + tid) * ldb + k0;
    const uint32_t bb = sbase + 2 * TILE_A;
#pragma unroll
    for (int c = 0; c < 4; c++) {
        const uint32_t d = toff((uint32_t)tid, (uint32_t)c, 7);
        CP16(bb + d,           b0 + c * 8);
        CP16(bb + TILE_BB + d, b1 + c * 8);
    }
}

// ---------------------------------------------------------------------------
// Split-bf16 MMA mainloop: acc = sum_k (Ah+Al)[m,k]*(Bh+Bl)[n,k] (Al*Bl dropped)
// 8 warps: 2x4 grid, 64x64 warp tiles. acc[4][8][4] per thread. 4-stage ring.
// ---------------------------------------------------------------------------
__device__ __forceinline__ void run_mainloop(
    const __nv_bfloat16* __restrict__ Ah, const __nv_bfloat16* __restrict__ Al,
    long lda, long m0,
    const __nv_bfloat16* __restrict__ Bh, const __nv_bfloat16* __restrict__ Bl,
    long ldb, long n0,
    int K, char* smem, float acc[4][8][4])
{
    const int tid = threadIdx.x;
    const int l   = tid & 31;
    const int wid = tid >> 5;
    const int wr  = wid >> 2;   // 0..1  (M)
    const int wc  = wid & 3;    // 0..3  (N)
    const uint32_t sb = smem_u32(smem);

#pragma unroll
    for (int mf = 0; mf < 4; mf++)
#pragma unroll
        for (int nf = 0; nf < 8; nf++)
#pragma unroll
            for (int i = 0; i < 4; i++) acc[mf][nf][i] = 0.f;

    const int NK = K / BKH;

    // prologue: fill 3 stages
#pragma unroll
    for (int s = 0; s < 3; s++) {
        stage_load(sb + s * STAGE_B, Ah, Al, lda, m0, Bh, Bl, ldb, n0,
                   (long)s * BKH, tid);
        CP_COMMIT();
    }

    // ldmatrix address components
    const uint32_t rAl = (uint32_t)(l & 15);                   // + mf*16 (row)
    const uint32_t cA0 = (uint32_t)(l >> 4) + 4u * (uint32_t)wr;      // + ks*2
    const uint32_t rB0 = (uint32_t)((wc & 1) * 64 + (l & 7) + ((l >> 4) << 3)); // + pr*16
    const uint32_t cB0 = (uint32_t)((l >> 3) & 1) + 4u * (uint32_t)(wc >> 1);   // + ks*2
    const uint32_t x7  = (uint32_t)(l & 7);

    for (int kt = 0; kt < NK; kt++) {
        CP_WAIT(2);
        __syncthreads();
        if (kt + 3 < NK)
            stage_load(sb + ((kt + 3) & 3) * STAGE_B,
                       Ah, Al, lda, m0, Bh, Bl, ldb, n0,
                       (long)(kt + 3) * BKH, tid);
        CP_COMMIT();   // unconditional: keeps wait_group bookkeeping uniform

        const uint32_t st  = sb + (kt & 3) * STAGE_B;
        const uint32_t aHi = st,              aLo = st + TILE_A;
        const uint32_t bHi = st + 2 * TILE_A, bLo = bHi + TILE_BB;

#pragma unroll
        for (int ks = 0; ks < 2; ks++) {
            uint32_t ah[4][4], al_[4][4], bh[4][4], bl_[4][4];
            const uint32_t cA = (cA0 + ks * 2) ;
#pragma unroll
            for (int mf = 0; mf < 4; mf++) {
                const uint32_t off = (rAl + mf * 16) * 128u + ((cA ^ x7) * 16u);
                ldm4(ah[mf],  aHi + off);
                ldm4(al_[mf], aLo + off);
            }
            const uint32_t cB = (cB0 + ks * 2);
#pragma unroll
            for (int pr = 0; pr < 4; pr++) {
                const uint32_t off = (rB0 + pr * 16) * 128u + ((cB ^ x7) * 16u);
                ldm4(bh[pr],  bHi + off);
                ldm4(bl_[pr], bLo + off);
            }
#pragma unroll
            for (int mf = 0; mf < 4; mf++)
#pragma unroll
                for (int nf = 0; nf < 8; nf++)
                    mma16(acc[mf][nf], ah[mf], &bh[nf >> 1][(nf & 1) * 2]);
#pragma unroll
            for (int mf = 0; mf < 4; mf++)
#pragma unroll
                for (int nf = 0; nf < 8; nf++)
                    mma16(acc[mf][nf], al_[mf], &bh[nf >> 1][(nf & 1) * 2]);
#pragma unroll
            for (int mf = 0; mf < 4; mf++)
#pragma unroll
                for (int nf = 0; nf < 8; nf++)
                    mma16(acc[mf][nf], ah[mf], &bl_[nf >> 1][(nf & 1) * 2]);
        }
    }
}

// ---------------------------------------------------------------------------
// Conversion: x -> (hi, lo) bf16
// ---------------------------------------------------------------------------
__global__ void __launch_bounds__(256) convert_x_kernel(const float* __restrict__ x)
{
    const size_t i = ((size_t)blockIdx.x * 256 + threadIdx.x) * 4;
    float4 v = *(const float4*)(x + i);
    __nv_bfloat16 h0 = __float2bfloat16(v.x), h1 = __float2bfloat16(v.y);
    __nv_bfloat16 h2 = __float2bfloat16(v.z), h3 = __float2bfloat16(v.w);
    *(__nv_bfloat162*)(g_xh + i)     = __halves2bfloat162(h0, h1);
    *(__nv_bfloat162*)(g_xh + i + 2) = __halves2bfloat162(h2, h3);
    *(__nv_bfloat162*)(g_xl + i) =
        __floats2bfloat162_rn(v.x - __bfloat162float(h0), v.y - __bfloat162float(h1));
    *(__nv_bfloat162*)(g_xl + i + 2) =
        __floats2bfloat162_rn(v.z - __bfloat162float(h2), v.w - __bfloat162float(h3));
}

// Weights: transpose [k][n] -> [n][k] and split hi/lo
__global__ void __launch_bounds__(256) convert_w_kernel(
    const float* __restrict__ Wq, const float* __restrict__ Wk, const float* __restrict__ Wv)
{
    __shared__ float t[32][33];
    const int z = blockIdx.z;
    const float* W = (z == 0) ? Wq : (z == 1) ? Wk : Wv;
    __nv_bfloat16* oh = g_wth[z];
    __nv_bfloat16* ol = g_wtl[z];
    const int tx = threadIdx.x, ty = threadIdx.y;
    const int nb = blockIdx.x * 32, kb = blockIdx.y * 32;
#pragma unroll
    for (int i = 0; i < 32; i += 8)
        t[ty + i][tx] = W[(size_t)(kb + ty + i) * DM + nb + tx];
    __syncthreads();
#pragma unroll
    for (int i = 0; i < 32; i += 8) {
        float f = t[tx][ty + i];   // = W[kb+tx][nb+ty+i]
        __nv_bfloat16 h = __float2bfloat16(f);
        const size_t o = (size_t)(nb + ty + i) * DM + kb + tx;
        oh[o] = h;
        ol[o] = __float2bfloat16(f - __bfloat162float(h));
    }
}

// ---------------------------------------------------------------------------
// GEMM 1: QKV. A = x[8192,1024], B = W^T[1024,1024]. z = {Q,K,V}.
// ---------------------------------------------------------------------------
__global__ void __launch_bounds__(NTHREADS, 1) qkv_kernel(
    const float* __restrict__ bq, const float* __restrict__ bk, const float* __restrict__ bv)
{
    extern __shared__ __align__(1024) char smem[];
    const int z = blockIdx.z;
    const long m0 = (long)blockIdx.y * BM;
    const long n0 = (long)blockIdx.x * BN;
    float acc[4][8][4];
    run_mainloop(g_xh, g_xl, DM, m0, g_wth[z], g_wtl[z], DM, n0, DM, smem, acc);

    const float* bias = (z == 0) ? bq : (z == 1) ? bk : bv;
    const int l = threadIdx.x & 31, wid = threadIdx.x >> 5;
    const long rbase = m0 + (wid >> 2) * 64 + (l >> 2);
    const long cbase = n0 + (wid & 3) * 64 + 2 * (l & 3);

#pragma unroll
    for (int mf = 0; mf < 4; mf++)
#pragma unroll
        for (int nf = 0; nf < 8; nf++)
#pragma unroll
            for (int h = 0; h < 2; h++) {
                const long m = rbase + mf * 16 + h * 8;
                const long n = cbase + nf * 8;
                float f0 = acc[mf][nf][h * 2 + 0] + bias[n];
                float f1 = acc[mf][nf][h * 2 + 1] + bias[n + 1];
                __nv_bfloat16 h0 = __float2bfloat16(f0);
                __nv_bfloat16 h1 = __float2bfloat16(f1);
                __nv_bfloat16 l0 = __float2bfloat16(f0 - __bfloat162float(h0));
                __nv_bfloat16 l1 = __float2bfloat16(f1 - __bfloat162float(h1));
                if (z < 2) {
                    __nv_bfloat16* oh = (z == 0) ? g_qh : g_kh;
                    __nv_bfloat16* ol = (z == 0) ? g_ql : g_kl;
                    *(__nv_bfloat162*)(oh + (size_t)m * DM + n) = __halves2bfloat162(h0, h1);
                    *(__nv_bfloat162*)(ol + (size_t)m * DM + n) = __halves2bfloat162(l0, l1);
                } else {
                    const long b = m >> 11, nrow = m & (SEQ - 1);
                    const size_t o = ((size_t)b * DM + n) * SEQ + nrow;
                    g_vth[o] = h0;  g_vth[o + SEQ] = h1;
                    g_vtl[o] = l0;  g_vtl[o + SEQ] = l1;
                }
            }
}

// ---------------------------------------------------------------------------
// GEMM 2: S = scale * Q K^T per batch (fp32 out)
// ---------------------------------------------------------------------------
__global__ void __launch_bounds__(NTHREADS, 1) qk_kernel()
{
    extern __shared__ __align__(1024) char smem[];
    const int b = blockIdx.z;
    const long m0 = (long)blockIdx.y * BM;
    const long n0 = (long)blockIdx.x * BN;
    const size_t boff = (size_t)b * SEQ * DM;
    float acc[4][8][4];
    run_mainloop(g_qh + boff, g_ql + boff, DM, m0,
                 g_kh + boff, g_kl + boff, DM, n0, DM, smem, acc);

    float* sp = g_s + (size_t)b * SEQ * SEQ;
    const int l = threadIdx.x & 31, wid = threadIdx.x >> 5;
    const long rbase = m0 + (wid >> 2) * 64 + (l >> 2);
    const long cbase = n0 + (wid & 3) * 64 + 2 * (l & 3);
#pragma unroll
    for (int mf = 0; mf < 4; mf++)
#pragma unroll
        for (int nf = 0; nf < 8; nf++)
#pragma unroll
            for (int h = 0; h < 2; h++) {
                const long m = rbase + mf * 16 + h * 8;
                const long n = cbase + nf * 8;
                float2 v;
                v.x = acc[mf][nf][h * 2 + 0] * 0.03125f;
                v.y = acc[mf][nf][h * 2 + 1] * 0.03125f;
                *(float2*)(sp + (size_t)m * SEQ + n) = v;
            }
}

// ---------------------------------------------------------------------------
// Softmax rows of S -> P split hi/lo bf16
// ---------------------------------------------------------------------------
__global__ void __launch_bounds__(256) softmax_kernel()
{
    const size_t row = blockIdx.x;
    const float* p = g_s + row * (size_t)SEQ;
    __nv_bfloat16* oh = g_ph + row * (size_t)SEQ;
    __nv_bfloat16* ol = g_pl + row * (size_t)SEQ;
    const int tid = threadIdx.x;
    const int lane = tid & 31, warp = tid >> 5;
    __shared__ float red[8];

    float4 v0 = ((const float4*)p)[tid];
    float4 v1 = ((const float4*)p)[tid + 256];

    float mx = fmaxf(fmaxf(fmaxf(v0.x, v0.y), fmaxf(v0.z, v0.w)),
                     fmaxf(fmaxf(v1.x, v1.y), fmaxf(v1.z, v1.w)));
#pragma unroll
    for (int o = 16; o > 0; o >>= 1)
        mx = fmaxf(mx, __shfl_xor_sync(0xffffffffu, mx, o));
    if (lane == 0) red[warp] = mx;
    __syncthreads();
    float m = red[0];
#pragma unroll
    for (int i = 1; i < 8; i++) m = fmaxf(m, red[i]);
    __syncthreads();

    float e[8];
    e[0] = __expf(v0.x - m); e[1] = __expf(v0.y - m);
    e[2] = __expf(v0.z - m); e[3] = __expf(v0.w - m);
    e[4] = __expf(v1.x - m); e[5] = __expf(v1.y - m);
    e[6] = __expf(v1.z - m); e[7] = __expf(v1.w - m);
    float s = ((e[0] + e[1]) + (e[2] + e[3])) + ((e[4] + e[5]) + (e[6] + e[7]));
#pragma unroll
    for (int o = 16; o > 0; o >>= 1)
        s += __shfl_xor_sync(0xffffffffu, s, o);
    if (lane == 0) red[warp] = s;
    __syncthreads();
    float tot = red[0];
#pragma unroll
    for (int i = 1; i < 8; i++) tot += red[i];
    const float inv = 1.0f / tot;

#pragma unroll
    for (int j = 0; j < 2; j++) {
        const int base = (j == 0) ? tid * 4 : (tid + 256) * 4;
        float p0 = e[j * 4 + 0] * inv, p1 = e[j * 4 + 1] * inv;
        float p2 = e[j * 4 + 2] * inv, p3 = e[j * 4 + 3] * inv;
        __nv_bfloat16 h0 = __float2bfloat16(p0), h1 = __float2bfloat16(p1);
        __nv_bfloat16 h2 = __float2bfloat16(p2), h3 = __float2bfloat16(p3);
        *(__nv_bfloat162*)(oh + base)     = __halves2bfloat162(h0, h1);
        *(__nv_bfloat162*)(oh + base + 2) = __halves2bfloat162(h2, h3);
        *(__nv_bfloat162*)(ol + base) =
            __floats2bfloat162_rn(p0 - __bfloat162float(h0), p1 - __bfloat162float(h1));
        *(__nv_bfloat162*)(ol + base + 2) =
            __floats2bfloat162_rn(p2 - __bfloat162float(h2), p3 - __bfloat162float(h3));
    }
}

// ---------------------------------------------------------------------------
// GEMM 3: O = P V per batch. A = P[2048,2048], B = V^T[1024,2048]. fp32 out.
// ---------------------------------------------------------------------------
__global__ void __launch_bounds__(NTHREADS, 1) pv_kernel(float* __restrict__ out)
{
    extern __shared__ __align__(1024) char smem[];
    const int b = blockIdx.z;
    const long m0 = (long)blockIdx.y * BM;
    const long n0 = (long)blockIdx.x * BN;
    const size_t poff = (size_t)b * SEQ * SEQ;
    const size_t voff = (size_t)b * DM * SEQ;
    float acc[4][8][4];
    run_mainloop(g_ph + poff, g_pl + poff, SEQ, m0,
                 g_vth + voff, g_vtl + voff, SEQ, n0, SEQ, smem, acc);

    float* op = out + (size_t)b * SEQ * DM;
    const int l = threadIdx.x & 31, wid = threadIdx.x >> 5;
    const long rbase = m0 + (wid >> 2) * 64 + (l >> 2);
    const long cbase = n0 + (wid & 3) * 64 + 2 * (l & 3);
#pragma unroll
    for (int mf = 0; mf < 4; mf++)
#pragma unroll
        for (int nf = 0; nf < 8; nf++)
#pragma unroll
            for (int h = 0; h < 2; h++) {
                const long m = rbase + mf * 16 + h * 8;
                const long n = cbase + nf * 8;
                float2 v;
                v.x = acc[mf][nf][h * 2 + 0];
                v.y = acc[mf][nf][h * 2 + 1];
                *(float2*)(op + (size_t)m * DM + n) = v;
            }
}

// ---------------------------------------------------------------------------
extern "C" void kernel_launch(void* const* d_in, const int* in_sizes, int n_in,
                              void* d_out, int out_size)
{
    (void)in_sizes; (void)n_in; (void)out_size;
    const float* x  = (const float*)d_in[0];
    const float* Wq = (const float*)d_in[1];
    const float* Wk = (const float*)d_in[2];
    const float* Wv = (const float*)d_in[3];
    const float* bq = (const float*)d_in[4];
    const float* bk = (const float*)d_in[5];
    const float* bv = (const float*)d_in[6];
    float* out = (float*)d_out;

    cudaFuncSetAttribute(qkv_kernel, cudaFuncAttributeMaxDynamicSharedMemorySize, SMEM_TOTAL);
    cudaFuncSetAttribute(qk_kernel,  cudaFuncAttributeMaxDynamicSharedMemorySize, SMEM_TOTAL);
    cudaFuncSetAttribute(pv_kernel,  cudaFuncAttributeMaxDynamicSharedMemorySize, SMEM_TOTAL);

    convert_x_kernel<<<(TOKENS * DM) / (256 * 4), 256>>>(x);
    convert_w_kernel<<<dim3(DM / 32, DM / 32, 3), dim3(32, 8)>>>(Wq, Wk, Wv);
    qkv_kernel<<<dim3(DM / BN, TOKENS / BM, 3), NTHREADS, SMEM_TOTAL>>>(bq, bk, bv);
    qk_kernel<<<dim3(SEQ / BN, SEQ / BM, BATCH), NTHREADS, SMEM_TOTAL>>>();
    softmax_kernel<<<BATCH * SEQ, 256>>>();
    pv_kernel<<<dim3(DM / BN, SEQ / BM, BATCH), NTHREADS, SMEM_TOTAL>>>(out);
}

// round 13
// speedup vs baseline: 1.2608x; 1.2608x over previous
#include <cuda_runtime.h>
#include <cuda_bf16.h>
#include <cstdint>

#define BATCH 4
#define SEQ   2048
#define DM    1024
#define TOKENS (BATCH * SEQ)   // 8192

#define BM 128
#define BN 128
#define BKH 64                        // K per stage (bf16 elements)
#define STAGES 3
#define NTHREADS 256
#define TILE_B  (BM * BKH * 2)        // 16384 bytes per tile
#define STAGE_B (4 * TILE_B)          // Ah, Al, Bh, Bl = 65536
#define SMEM_TOTAL (STAGES * STAGE_B) // 196608

// ---------------------------------------------------------------------------
// Scratch (__device__ globals; 16B-aligned)
// ---------------------------------------------------------------------------
__device__ __align__(16) __nv_bfloat16 g_xh[(size_t)TOKENS * DM];
__device__ __align__(16) __nv_bfloat16 g_xl[(size_t)TOKENS * DM];
__device__ __align__(16) __nv_bfloat16 g_wth[3][(size_t)DM * DM];  // W^T [n][k]
__device__ __align__(16) __nv_bfloat16 g_wtl[3][(size_t)DM * DM];
__device__ __align__(16) __nv_bfloat16 g_qh[(size_t)TOKENS * DM];
__device__ __align__(16) __nv_bfloat16 g_ql[(size_t)TOKENS * DM];
__device__ __align__(16) __nv_bfloat16 g_kh[(size_t)TOKENS * DM];
__device__ __align__(16) __nv_bfloat16 g_kl[(size_t)TOKENS * DM];
__device__ __align__(16) __nv_bfloat16 g_vth[(size_t)BATCH * DM * SEQ]; // V^T [e][n]
__device__ __align__(16) __nv_bfloat16 g_vtl[(size_t)BATCH * DM * SEQ];
__device__ __align__(16) float         g_s [(size_t)BATCH * SEQ * SEQ];
__device__ __align__(16) __nv_bfloat16 g_ph[(size_t)BATCH * SEQ * SEQ];
__device__ __align__(16) __nv_bfloat16 g_pl[(size_t)BATCH * SEQ * SEQ];

// ---------------------------------------------------------------------------
// PTX helpers — baseline ISA only (compiles under compute_103)
// ---------------------------------------------------------------------------
__device__ __forceinline__ uint32_t smem_u32(const void* p) {
    uint32_t a;
    asm("{ .reg .u64 t; cvta.to.shared.u64 t, %1; cvt.u32.u64 %0, t; }"
        : "=r"(a) : "l"(p));
    return a;
}

#define CP16(dst, src) \
    asm volatile("cp.async.cg.shared.global [%0], [%1], 16;" \
        :: "r"(dst), "l"(src) : "memory")
#define CP_COMMIT() asm volatile("cp.async.commit_group;" ::: "memory")
#define CP_WAIT(N)  asm volatile("cp.async.wait_group %0;" :: "n"(N) : "memory")

__device__ __forceinline__ void ldm4(uint32_t* r, uint32_t addr) {
    asm volatile("ldmatrix.sync.aligned.m8n8.x4.shared.b16 {%0,%1,%2,%3}, [%4];"
        : "=r"(r[0]), "=r"(r[1]), "=r"(r[2]), "=r"(r[3]) : "r"(addr));
}

__device__ __forceinline__ void mma16(float* d, const uint32_t* a, const uint32_t* b) {
    asm volatile(
        "mma.sync.aligned.m16n8k16.row.col.f32.bf16.bf16.f32 "
        "{%0,%1,%2,%3}, {%4,%5,%6,%7}, {%8,%9}, {%0,%1,%2,%3};"
        : "+f"(d[0]), "+f"(d[1]), "+f"(d[2]), "+f"(d[3])
        : "r"(a[0]), "r"(a[1]), "r"(a[2]), "r"(a[3]), "r"(b[0]), "r"(b[1]));
}

// Tile: 128 rows x 64 bf16 (128B rows), SW128 swizzle: chunk' = chunk ^ (row&7)
__device__ __forceinline__ uint32_t sw_off(uint32_t r, uint32_t c) {
    return r * 128u + ((c ^ (r & 7u)) * 16u);
}

// ---------------------------------------------------------------------------
// Issue cp.async loads for one stage (Ah, Al, Bh, Bl K-major 128x64 tiles)
// ---------------------------------------------------------------------------
__device__ __forceinline__ void stage_load(
    uint32_t sbase,
    const __nv_bfloat16* __restrict__ Ah, const __nv_bfloat16* __restrict__ Al,
    long lda, long m0,
    const __nv_bfloat16* __restrict__ Bh, const __nv_bfloat16* __restrict__ Bl,
    long ldb, long n0,
    long k0, int tid)
{
    const uint32_t r  = (uint32_t)(tid >> 1);
    const uint32_t c0 = (uint32_t)((tid & 1) * 4);
    const __nv_bfloat16* s0 = Ah + (m0 + r) * lda + k0;
    const __nv_bfloat16* s1 = Al + (m0 + r) * lda + k0;
    const __nv_bfloat16* s2 = Bh + (n0 + r) * ldb + k0;
    const __nv_bfloat16* s3 = Bl + (n0 + r) * ldb + k0;
#pragma unroll
    for (int i = 0; i < 4; i++) {
        const uint32_t c = c0 + i;
        const uint32_t d = sw_off(r, c);
        CP16(sbase + 0 * TILE_B + d, s0 + c * 8);
        CP16(sbase + 1 * TILE_B + d, s1 + c * 8);
        CP16(sbase + 2 * TILE_B + d, s2 + c * 8);
        CP16(sbase + 3 * TILE_B + d, s3 + c * 8);
    }
}

// ---------------------------------------------------------------------------
// Split-bf16 MMA mainloop with FRAGMENT DOUBLE-BUFFERING:
// prefetch the next ks fragment set (LDSM) before issuing this ks's MMAs,
// so LDSM latency hides under 48 MMAs of tensor-pipe time per warp.
// 8 warps: 2x4 grid, 64x32 warp tiles. acc[4][4][4] per thread.
// ---------------------------------------------------------------------------
__device__ __forceinline__ void run_mainloop(
    const __nv_bfloat16* __restrict__ Ah, const __nv_bfloat16* __restrict__ Al,
    long lda, long m0,
    const __nv_bfloat16* __restrict__ Bh, const __nv_bfloat16* __restrict__ Bl,
    long ldb, long n0,
    int K, char* smem, float acc[4][4][4])
{
    const int tid = threadIdx.x;
    const int l   = tid & 31;
    const int wid = tid >> 5;
    const int wr  = wid >> 2;   // 0..1
    const int wc  = wid & 3;    // 0..3
    const uint32_t sb = smem_u32(smem);

#pragma unroll
    for (int mf = 0; mf < 4; mf++)
#pragma unroll
        for (int nf = 0; nf < 4; nf++)
#pragma unroll
            for (int i = 0; i < 4; i++) acc[mf][nf][i] = 0.f;

    const int NK = K / BKH;

    // prologue: fill 2 of 3 stages
    stage_load(sb,           Ah, Al, lda, m0, Bh, Bl, ldb, n0, 0,   tid);
    CP_COMMIT();
    stage_load(sb + STAGE_B, Ah, Al, lda, m0, Bh, Bl, ldb, n0, BKH, tid);
    CP_COMMIT();

    // per-thread ldmatrix address components
    const uint32_t rA    = (uint32_t)(wr * 64 + (l & 15));        // + mf*16
    const uint32_t cAadd = (uint32_t)(l >> 4);                    // + ks*2
    const uint32_t xorA  = rA & 7u;
    const uint32_t rB    = (uint32_t)(wc * 32 + (l & 7) + ((l >> 4) << 3)); // + pr*16
    const uint32_t cBadd = (uint32_t)((l >> 3) & 1);
    const uint32_t xorB  = rB & 7u;

    // double-buffered fragments
    uint32_t ah[2][4][4], al_[2][4][4], bh[2][2][4], bl_[2][2][4];

    auto frag_load = [&](int b, uint32_t st, int ks) {
        const uint32_t aHi = st,              aLo = st + TILE_B;
        const uint32_t bHi = st + 2 * TILE_B, bLo = st + 3 * TILE_B;
        const uint32_t cA = (uint32_t)(ks * 2) + cAadd;
#pragma unroll
        for (int mf = 0; mf < 4; mf++) {
            const uint32_t off = (rA + mf * 16) * 128u + ((cA ^ xorA) * 16u);
            ldm4(ah[b][mf],  aHi + off);
            ldm4(al_[b][mf], aLo + off);
        }
        const uint32_t cB = (uint32_t)(ks * 2) + cBadd;
#pragma unroll
        for (int pr = 0; pr < 2; pr++) {
            const uint32_t off = (rB + pr * 16) * 128u + ((cB ^ xorB) * 16u);
            ldm4(bh[b][pr],  bHi + off);
            ldm4(bl_[b][pr], bLo + off);
        }
    };

    // wait for stage 0, preload its first fragment set
    CP_WAIT(1);
    __syncthreads();
    frag_load(0, sb, 0);

    int s_cur = 0;                 // stage slot for kt
    for (int kt = 0; kt < NK; kt++) {
        const uint32_t st = sb + s_cur * STAGE_B;
#pragma unroll
        for (int ks = 0; ks < 4; ks++) {
            const int cur = ks & 1, nxt = cur ^ 1;
            if (ks < 3) {
                frag_load(nxt, st, ks + 1);
            } else {
                // refill the slot freed at kt-1 with stage kt+2
                if (kt + 2 < NK) {
                    int s_fill = s_cur + 2; if (s_fill >= STAGES) s_fill -= STAGES;
                    stage_load(sb + s_fill * STAGE_B,
                               Ah, Al, lda, m0, Bh, Bl, ldb, n0,
                               (long)(kt + 2) * BKH, tid);
                }
                CP_COMMIT();       // unconditional: uniform group bookkeeping
                if (kt + 1 < NK) {
                    CP_WAIT(1);    // stage kt+1 resident
                    __syncthreads();
                    int s_nxt = s_cur + 1; if (s_nxt >= STAGES) s_nxt -= STAGES;
                    frag_load(nxt, sb + s_nxt * STAGE_B, 0);
                }
            }
            // 48 MMAs on the current fragment set (term-major)
#pragma unroll
            for (int mf = 0; mf < 4; mf++)
#pragma unroll
                for (int nf = 0; nf < 4; nf++)
                    mma16(acc[mf][nf], ah[cur][mf], &bh[cur][nf >> 1][(nf & 1) * 2]);
#pragma unroll
            for (int mf = 0; mf < 4; mf++)
#pragma unroll
                for (int nf = 0; nf < 4; nf++)
                    mma16(acc[mf][nf], al_[cur][mf], &bh[cur][nf >> 1][(nf & 1) * 2]);
#pragma unroll
            for (int mf = 0; mf < 4; mf++)
#pragma unroll
                for (int nf = 0; nf < 4; nf++)
                    mma16(acc[mf][nf], ah[cur][mf], &bl_[cur][nf >> 1][(nf & 1) * 2]);
        }
        if (++s_cur >= STAGES) s_cur -= STAGES;
    }
}

// ---------------------------------------------------------------------------
// Conversion: x -> (hi, lo) bf16
// ---------------------------------------------------------------------------
__global__ void __launch_bounds__(256) convert_x_kernel(const float* __restrict__ x)
{
    const size_t i = ((size_t)blockIdx.x * 256 + threadIdx.x) * 4;
    float4 v = *(const float4*)(x + i);
    __nv_bfloat16 h0 = __float2bfloat16(v.x), h1 = __float2bfloat16(v.y);
    __nv_bfloat16 h2 = __float2bfloat16(v.z), h3 = __float2bfloat16(v.w);
    *(__nv_bfloat162*)(g_xh + i)     = __halves2bfloat162(h0, h1);
    *(__nv_bfloat162*)(g_xh + i + 2) = __halves2bfloat162(h2, h3);
    *(__nv_bfloat162*)(g_xl + i) =
        __floats2bfloat162_rn(v.x - __bfloat162float(h0), v.y - __bfloat162float(h1));
    *(__nv_bfloat162*)(g_xl + i + 2) =
        __floats2bfloat162_rn(v.z - __bfloat162float(h2), v.w - __bfloat162float(h3));
}

// Weights: transpose [k][n] -> [n][k] and split hi/lo
__global__ void __launch_bounds__(256) convert_w_kernel(
    const float* __restrict__ Wq, const float* __restrict__ Wk, const float* __restrict__ Wv)
{
    __shared__ float t[32][33];
    const int z = blockIdx.z;
    const float* W = (z == 0) ? Wq : (z == 1) ? Wk : Wv;
    __nv_bfloat16* oh = g_wth[z];
    __nv_bfloat16* ol = g_wtl[z];
    const int tx = threadIdx.x, ty = threadIdx.y;
    const int nb = blockIdx.x * 32, kb = blockIdx.y * 32;
#pragma unroll
    for (int i = 0; i < 32; i += 8)
        t[ty + i][tx] = W[(size_t)(kb + ty + i) * DM + nb + tx];
    __syncthreads();
#pragma unroll
    for (int i = 0; i < 32; i += 8) {
        float f = t[tx][ty + i];   // = W[kb+tx][nb+ty+i]
        __nv_bfloat16 h = __float2bfloat16(f);
        const size_t o = (size_t)(nb + ty + i) * DM + kb + tx;
        oh[o] = h;
        ol[o] = __float2bfloat16(f - __bfloat162float(h));
    }
}

// ---------------------------------------------------------------------------
// GEMM 1: QKV. A = x[8192,1024], B = W^T[1024,1024]. z = {Q,K,V}.
// ---------------------------------------------------------------------------
__global__ void __launch_bounds__(NTHREADS, 1) qkv_kernel(
    const float* __restrict__ bq, const float* __restrict__ bk, const float* __restrict__ bv)
{
    extern __shared__ __align__(1024) char smem[];
    const int z = blockIdx.z;
    const long m0 = (long)blockIdx.y * BM;
    const long n0 = (long)blockIdx.x * BN;
    float acc[4][4][4];
    run_mainloop(g_xh, g_xl, DM, m0, g_wth[z], g_wtl[z], DM, n0, DM, smem, acc);

    const float* bias = (z == 0) ? bq : (z == 1) ? bk : bv;
    const int l = threadIdx.x & 31, wid = threadIdx.x >> 5;
    const long rbase = m0 + (wid >> 2) * 64 + (l >> 2);
    const long cbase = n0 + (wid & 3) * 32 + 2 * (l & 3);

#pragma unroll
    for (int mf = 0; mf < 4; mf++)
#pragma unroll
        for (int nf = 0; nf < 4; nf++)
#pragma unroll
            for (int h = 0; h < 2; h++) {
                const long m = rbase + mf * 16 + h * 8;
                const long n = cbase + nf * 8;
                float f0 = acc[mf][nf][h * 2 + 0] + bias[n];
                float f1 = acc[mf][nf][h * 2 + 1] + bias[n + 1];
                __nv_bfloat16 h0 = __float2bfloat16(f0);
                __nv_bfloat16 h1 = __float2bfloat16(f1);
                __nv_bfloat16 l0 = __float2bfloat16(f0 - __bfloat162float(h0));
                __nv_bfloat16 l1 = __float2bfloat16(f1 - __bfloat162float(h1));
                if (z < 2) {
                    __nv_bfloat16* oh = (z == 0) ? g_qh : g_kh;
                    __nv_bfloat16* ol = (z == 0) ? g_ql : g_kl;
                    *(__nv_bfloat162*)(oh + (size_t)m * DM + n) = __halves2bfloat162(h0, h1);
                    *(__nv_bfloat162*)(ol + (size_t)m * DM + n) = __halves2bfloat162(l0, l1);
                } else {
                    const long b = m >> 11, nrow = m & (SEQ - 1);
                    const size_t o = ((size_t)b * DM + n) * SEQ + nrow;
                    g_vth[o] = h0;  g_vth[o + SEQ] = h1;
                    g_vtl[o] = l0;  g_vtl[o + SEQ] = l1;
                }
            }
}

// ---------------------------------------------------------------------------
// GEMM 2: S = scale * Q K^T per batch (fp32 out)
// ---------------------------------------------------------------------------
__global__ void __launch_bounds__(NTHREADS, 1) qk_kernel()
{
    extern __shared__ __align__(1024) char smem[];
    const int b = blockIdx.z;
    const long m0 = (long)blockIdx.y * BM;
    const long n0 = (long)blockIdx.x * BN;
    const size_t boff = (size_t)b * SEQ * DM;
    float acc[4][4][4];
    run_mainloop(g_qh + boff, g_ql + boff, DM, m0,
                 g_kh + boff, g_kl + boff, DM, n0, DM, smem, acc);

    float* sp = g_s + (size_t)b * SEQ * SEQ;
    const int l = threadIdx.x & 31, wid = threadIdx.x >> 5;
    const long rbase = m0 + (wid >> 2) * 64 + (l >> 2);
    const long cbase = n0 + (wid & 3) * 32 + 2 * (l & 3);
#pragma unroll
    for (int mf = 0; mf < 4; mf++)
#pragma unroll
        for (int nf = 0; nf < 4; nf++)
#pragma unroll
            for (int h = 0; h < 2; h++) {
                const long m = rbase + mf * 16 + h * 8;
                const long n = cbase + nf * 8;
                float2 v;
                v.x = acc[mf][nf][h * 2 + 0] * 0.03125f;
                v.y = acc[mf][nf][h * 2 + 1] * 0.03125f;
                *(float2*)(sp + (size_t)m * SEQ + n) = v;
            }
}

// ---------------------------------------------------------------------------
// Softmax rows of S -> P split hi/lo bf16
// ---------------------------------------------------------------------------
__global__ void __launch_bounds__(256) softmax_kernel()
{
    const size_t row = blockIdx.x;
    const float* p = g_s + row * (size_t)SEQ;
    __nv_bfloat16* oh = g_ph + row * (size_t)SEQ;
    __nv_bfloat16* ol = g_pl + row * (size_t)SEQ;
    const int tid = threadIdx.x;
    const int lane = tid & 31, warp = tid >> 5;
    __shared__ float red[8];

    float4 v0 = ((const float4*)p)[tid];
    float4 v1 = ((const float4*)p)[tid + 256];

    float mx = fmaxf(fmaxf(fmaxf(v0.x, v0.y), fmaxf(v0.z, v0.w)),
                     fmaxf(fmaxf(v1.x, v1.y), fmaxf(v1.z, v1.w)));
#pragma unroll
    for (int o = 16; o > 0; o >>= 1)
        mx = fmaxf(mx, __shfl_xor_sync(0xffffffffu, mx, o));
    if (lane == 0) red[warp] = mx;
    __syncthreads();
    float m = red[0];
#pragma unroll
    for (int i = 1; i < 8; i++) m = fmaxf(m, red[i]);
    __syncthreads();

    float e[8];
    e[0] = __expf(v0.x - m); e[1] = __expf(v0.y - m);
    e[2] = __expf(v0.z - m); e[3] = __expf(v0.w - m);
    e[4] = __expf(v1.x - m); e[5] = __expf(v1.y - m);
    e[6] = __expf(v1.z - m); e[7] = __expf(v1.w - m);
    float s = ((e[0] + e[1]) + (e[2] + e[3])) + ((e[4] + e[5]) + (e[6] + e[7]));
#pragma unroll
    for (int o = 16; o > 0; o >>= 1)
        s += __shfl_xor_sync(0xffffffffu, s, o);
    if (lane == 0) red[warp] = s;
    __syncthreads();
    float tot = red[0];
#pragma unroll
    for (int i = 1; i < 8; i++) tot += red[i];
    const float inv = 1.0f / tot;

#pragma unroll
    for (int j = 0; j < 2; j++) {
        const int base = (j == 0) ? tid * 4 : (tid + 256) * 4;
        float p0 = e[j * 4 + 0] * inv, p1 = e[j * 4 + 1] * inv;
        float p2 = e[j * 4 + 2] * inv, p3 = e[j * 4 + 3] * inv;
        __nv_bfloat16 h0 = __float2bfloat16(p0), h1 = __float2bfloat16(p1);
        __nv_bfloat16 h2 = __float2bfloat16(p2), h3 = __float2bfloat16(p3);
        *(__nv_bfloat162*)(oh + base)     = __halves2bfloat162(h0, h1);
        *(__nv_bfloat162*)(oh + base + 2) = __halves2bfloat162(h2, h3);
        *(__nv_bfloat162*)(ol + base) =
            __floats2bfloat162_rn(p0 - __bfloat162float(h0), p1 - __bfloat162float(h1));
        *(__nv_bfloat162*)(ol + base + 2) =
            __floats2bfloat162_rn(p2 - __bfloat162float(h2), p3 - __bfloat162float(h3));
    }
}

// ---------------------------------------------------------------------------
// GEMM 3: O = P V per batch. A = P[2048,2048], B = V^T[1024,2048]. fp32 out.
// ---------------------------------------------------------------------------
__global__ void __launch_bounds__(NTHREADS, 1) pv_kernel(float* __restrict__ out)
{
    extern __shared__ __align__(1024) char smem[];
    const int b = blockIdx.z;
    const long m0 = (long)blockIdx.y * BM;
    const long n0 = (long)blockIdx.x * BN;
    const size_t poff = (size_t)b * SEQ * SEQ;
    const size_t voff = (size_t)b * DM * SEQ;
    float acc[4][4][4];
    run_mainloop(g_ph + poff, g_pl + poff, SEQ, m0,
                 g_vth + voff, g_vtl + voff, SEQ, n0, SEQ, smem, acc);

    float* op = out + (size_t)b * SEQ * DM;
    const int l = threadIdx.x & 31, wid = threadIdx.x >> 5;
    const long rbase = m0 + (wid >> 2) * 64 + (l >> 2);
    const long cbase = n0 + (wid & 3) * 32 + 2 * (l & 3);
#pragma unroll
    for (int mf = 0; mf < 4; mf++)
#pragma unroll
        for (int nf = 0; nf < 4; nf++)
#pragma unroll
            for (int h = 0; h < 2; h++) {
                const long m = rbase + mf * 16 + h * 8;
                const long n = cbase + nf * 8;
                float2 v;
                v.x = acc[mf][nf][h * 2 + 0];
                v.y = acc[mf][nf][h * 2 + 1];
                *(float2*)(op + (size_t)m * DM + n) = v;
            }
}

// ---------------------------------------------------------------------------
extern "C" void kernel_launch(void* const* d_in, const int* in_sizes, int n_in,
                              void* d_out, int out_size)
{
    (void)in_sizes; (void)n_in; (void)out_size;
    const float* x  = (const float*)d_in[0];
    const float* Wq = (const float*)d_in[1];
    const float* Wk = (const float*)d_in[2];
    const float* Wv = (const float*)d_in[3];
    const float* bq = (const float*)d_in[4];
    const float* bk = (const float*)d_in[5];
    const float* bv = (const float*)d_in[6];
    float* out = (float*)d_out;

    cudaFuncSetAttribute(qkv_kernel, cudaFuncAttributeMaxDynamicSharedMemorySize, SMEM_TOTAL);
    cudaFuncSetAttribute(qk_kernel,  cudaFuncAttributeMaxDynamicSharedMemorySize, SMEM_TOTAL);
    cudaFuncSetAttribute(pv_kernel,  cudaFuncAttributeMaxDynamicSharedMemorySize, SMEM_TOTAL);

    convert_x_kernel<<<(TOKENS * DM) / (256 * 4), 256>>>(x);
    convert_w_kernel<<<dim3(DM / 32, DM / 32, 3), dim3(32, 8)>>>(Wq, Wk, Wv);
    qkv_kernel<<<dim3(DM / BN, TOKENS / BM, 3), NTHREADS, SMEM_TOTAL>>>(bq, bk, bv);
    qk_kernel<<<dim3(SEQ / BN, SEQ / BM, BATCH), NTHREADS, SMEM_TOTAL>>>();
    softmax_kernel<<<BATCH * SEQ, 256>>>();
    pv_kernel<<<dim3(DM / BN, SEQ / BM, BATCH), NTHREADS, SMEM_TOTAL>>>(out);
}

// round 14
// speedup vs baseline: 1.3139x; 1.0421x over previous
#include <cuda_runtime.h>
#include <cuda_bf16.h>
#include <cstdint>

#define BATCH 4
#define SEQ   2048
#define DM    1024
#define TOKENS (BATCH * SEQ)   // 8192

#define BM 128
#define BN 128
#define BKH 32                        // K per stage (bf16 elements)
#define STAGES 3
#define NTHREADS 256
#define TILE_B  (BM * BKH * 2)        // 8192 bytes per tile (packed 64 rows x 128B)
#define STAGE_B (4 * TILE_B)          // Ah, Al, Bh, Bl = 32768
#define SMEM_TOTAL (STAGES * STAGE_B) // 98304 -> 2 CTAs/SM

// ---------------------------------------------------------------------------
// Scratch (__device__ globals; 16B-aligned)
// ---------------------------------------------------------------------------
__device__ __align__(16) __nv_bfloat16 g_xh[(size_t)TOKENS * DM];
__device__ __align__(16) __nv_bfloat16 g_xl[(size_t)TOKENS * DM];
__device__ __align__(16) __nv_bfloat16 g_wth[3][(size_t)DM * DM];  // W^T [n][k]
__device__ __align__(16) __nv_bfloat16 g_wtl[3][(size_t)DM * DM];
__device__ __align__(16) __nv_bfloat16 g_qh[(size_t)TOKENS * DM];
__device__ __align__(16) __nv_bfloat16 g_ql[(size_t)TOKENS * DM];
__device__ __align__(16) __nv_bfloat16 g_kh[(size_t)TOKENS * DM];
__device__ __align__(16) __nv_bfloat16 g_kl[(size_t)TOKENS * DM];
__device__ __align__(16) __nv_bfloat16 g_vth[(size_t)BATCH * DM * SEQ]; // V^T [e][n]
__device__ __align__(16) __nv_bfloat16 g_vtl[(size_t)BATCH * DM * SEQ];
__device__ __align__(16) float         g_s [(size_t)BATCH * SEQ * SEQ];
__device__ __align__(16) __nv_bfloat16 g_ph[(size_t)BATCH * SEQ * SEQ];
__device__ __align__(16) __nv_bfloat16 g_pl[(size_t)BATCH * SEQ * SEQ];

// ---------------------------------------------------------------------------
// PTX helpers — baseline ISA only (compiles under compute_103)
// ---------------------------------------------------------------------------
__device__ __forceinline__ uint32_t smem_u32(const void* p) {
    uint32_t a;
    asm("{ .reg .u64 t; cvta.to.shared.u64 t, %1; cvt.u32.u64 %0, t; }"
        : "=r"(a) : "l"(p));
    return a;
}

#define CP16(dst, src) \
    asm volatile("cp.async.cg.shared.global [%0], [%1], 16;" \
        :: "r"(dst), "l"(src) : "memory")
#define CP_COMMIT() asm volatile("cp.async.commit_group;" ::: "memory")
#define CP_WAIT(N)  asm volatile("cp.async.wait_group %0;" :: "n"(N) : "memory")

__device__ __forceinline__ void ldm4(uint32_t* r, uint32_t addr) {
    asm volatile("ldmatrix.sync.aligned.m8n8.x4.shared.b16 {%0,%1,%2,%3}, [%4];"
        : "=r"(r[0]), "=r"(r[1]), "=r"(r[2]), "=r"(r[3]) : "r"(addr));
}

__device__ __forceinline__ void mma16(float* d, const uint32_t* a, const uint32_t* b) {
    asm volatile(
        "mma.sync.aligned.m16n8k16.row.col.f32.bf16.bf16.f32 "
        "{%0,%1,%2,%3}, {%4,%5,%6,%7}, {%8,%9}, {%0,%1,%2,%3};"
        : "+f"(d[0]), "+f"(d[1]), "+f"(d[2]), "+f"(d[3])
        : "r"(a[0]), "r"(a[1]), "r"(a[2]), "r"(a[3]), "r"(b[0]), "r"(b[1]));
}

// Tile of 128 rows x 32 bf16 packed as 64 rows x 128B with SW128 swizzle.
// prow = r & 63, chunk = c + 4*(r>>6); off = prow*128 + ((chunk ^ (prow&7))*16)
__device__ __forceinline__ uint32_t toff(uint32_t r, uint32_t c) {
    const uint32_t prow  = r & 63u;
    const uint32_t chunk = c + ((r >> 6) << 2);
    return prow * 128u + ((chunk ^ (prow & 7u)) * 16u);
}

// ---------------------------------------------------------------------------
// Stage load (256 threads): 4 tiles of 128x32 bf16, 2 cp16/thread/tile
// ---------------------------------------------------------------------------
__device__ __forceinline__ void stage_load(
    uint32_t sbase,
    const __nv_bfloat16* __restrict__ Ah, const __nv_bfloat16* __restrict__ Al,
    long lda, long m0,
    const __nv_bfloat16* __restrict__ Bh, const __nv_bfloat16* __restrict__ Bl,
    long ldb, long n0,
    long k0, int tid)
{
    const uint32_t r  = (uint32_t)(tid >> 1);
    const uint32_t c0 = (uint32_t)((tid & 1) * 2);
    const __nv_bfloat16* s0 = Ah + (m0 + r) * lda + k0;
    const __nv_bfloat16* s1 = Al + (m0 + r) * lda + k0;
    const __nv_bfloat16* s2 = Bh + (n0 + r) * ldb + k0;
    const __nv_bfloat16* s3 = Bl + (n0 + r) * ldb + k0;
#pragma unroll
    for (int i = 0; i < 2; i++) {
        const uint32_t c = c0 + i;
        const uint32_t d = toff(r, c);
        CP16(sbase + 0 * TILE_B + d, s0 + c * 8);
        CP16(sbase + 1 * TILE_B + d, s1 + c * 8);
        CP16(sbase + 2 * TILE_B + d, s2 + c * 8);
        CP16(sbase + 3 * TILE_B + d, s3 + c * 8);
    }
}

// ---------------------------------------------------------------------------
// Split-bf16 MMA mainloop: acc = sum_k (Ah+Al)[m,k]*(Bh+Bl)[n,k] (Al*Bl dropped)
// 8 warps: 2x4 grid, 64x32 warp tiles. acc[4][4][4]. Single-buffered frags
// (register cap 128 for 2 CTAs/SM); overlap comes from the co-resident CTA.
// ---------------------------------------------------------------------------
__device__ __forceinline__ void run_mainloop(
    const __nv_bfloat16* __restrict__ Ah, const __nv_bfloat16* __restrict__ Al,
    long lda, long m0,
    const __nv_bfloat16* __restrict__ Bh, const __nv_bfloat16* __restrict__ Bl,
    long ldb, long n0,
    int K, char* smem, float acc[4][4][4])
{
    const int tid = threadIdx.x;
    const int l   = tid & 31;
    const int wid = tid >> 5;
    const int wr  = wid >> 2;   // 0..1
    const int wc  = wid & 3;    // 0..3
    const uint32_t sb = smem_u32(smem);

#pragma unroll
    for (int mf = 0; mf < 4; mf++)
#pragma unroll
        for (int nf = 0; nf < 4; nf++)
#pragma unroll
            for (int i = 0; i < 4; i++) acc[mf][nf][i] = 0.f;

    const int NK = K / BKH;

    // prologue: fill 2 of 3 stages
    stage_load(sb,           Ah, Al, lda, m0, Bh, Bl, ldb, n0, 0,   tid);
    CP_COMMIT();
    stage_load(sb + STAGE_B, Ah, Al, lda, m0, Bh, Bl, ldb, n0, BKH, tid);
    CP_COMMIT();

    // per-thread ldmatrix address components
    const uint32_t rA    = (uint32_t)(wr * 64 + (l & 15));        // + mf*16
    const uint32_t cAadd = (uint32_t)(l >> 4);                    // + ks*2
    const uint32_t rB    = (uint32_t)(wc * 32 + (l & 7) + ((l >> 4) << 3)); // + pr*16
    const uint32_t cBadd = (uint32_t)((l >> 3) & 1);

    int s_cur = 0;
    for (int kt = 0; kt < NK; kt++) {
        CP_WAIT(1);
        __syncthreads();
        if (kt + 2 < NK) {
            int s_fill = s_cur + 2; if (s_fill >= STAGES) s_fill -= STAGES;
            stage_load(sb + s_fill * STAGE_B,
                       Ah, Al, lda, m0, Bh, Bl, ldb, n0,
                       (long)(kt + 2) * BKH, tid);
        }
        CP_COMMIT();   // unconditional: uniform group bookkeeping

        const uint32_t st  = sb + s_cur * STAGE_B;
        const uint32_t aHi = st,              aLo = st + TILE_B;
        const uint32_t bHi = st + 2 * TILE_B, bLo = st + 3 * TILE_B;

#pragma unroll
        for (int ks = 0; ks < 2; ks++) {
            uint32_t ah[4][4], al_[4][4], bh[2][4], bl_[2][4];
            const uint32_t cA = (uint32_t)(ks * 2) + cAadd;
#pragma unroll
            for (int mf = 0; mf < 4; mf++) {
                const uint32_t rr = rA + mf * 16;
                const uint32_t prow = rr & 63u;
                const uint32_t off = prow * 128u +
                    (((cA + ((rr >> 6) << 2)) ^ (prow & 7u)) * 16u);
                ldm4(ah[mf],  aHi + off);
                ldm4(al_[mf], aLo + off);
            }
            const uint32_t cB = (uint32_t)(ks * 2) + cBadd;
#pragma unroll
            for (int pr = 0; pr < 2; pr++) {
                const uint32_t rr = rB + pr * 16;
                const uint32_t prow = rr & 63u;
                const uint32_t off = prow * 128u +
                    (((cB + ((rr >> 6) << 2)) ^ (prow & 7u)) * 16u);
                ldm4(bh[pr],  bHi + off);
                ldm4(bl_[pr], bLo + off);
            }
#pragma unroll
            for (int mf = 0; mf < 4; mf++)
#pragma unroll
                for (int nf = 0; nf < 4; nf++)
                    mma16(acc[mf][nf], ah[mf], &bh[nf >> 1][(nf & 1) * 2]);
#pragma unroll
            for (int mf = 0; mf < 4; mf++)
#pragma unroll
                for (int nf = 0; nf < 4; nf++)
                    mma16(acc[mf][nf], al_[mf], &bh[nf >> 1][(nf & 1) * 2]);
#pragma unroll
            for (int mf = 0; mf < 4; mf++)
#pragma unroll
                for (int nf = 0; nf < 4; nf++)
                    mma16(acc[mf][nf], ah[mf], &bl_[nf >> 1][(nf & 1) * 2]);
        }
        if (++s_cur >= STAGES) s_cur -= STAGES;
    }
}

// ---------------------------------------------------------------------------
// Conversion: x -> (hi, lo) bf16
// ---------------------------------------------------------------------------
__global__ void __launch_bounds__(256) convert_x_kernel(const float* __restrict__ x)
{
    const size_t i = ((size_t)blockIdx.x * 256 + threadIdx.x) * 4;
    float4 v = *(const float4*)(x + i);
    __nv_bfloat16 h0 = __float2bfloat16(v.x), h1 = __float2bfloat16(v.y);
    __nv_bfloat16 h2 = __float2bfloat16(v.z), h3 = __float2bfloat16(v.w);
    *(__nv_bfloat162*)(g_xh + i)     = __halves2bfloat162(h0, h1);
    *(__nv_bfloat162*)(g_xh + i + 2) = __halves2bfloat162(h2, h3);
    *(__nv_bfloat162*)(g_xl + i) =
        __floats2bfloat162_rn(v.x - __bfloat162float(h0), v.y - __bfloat162float(h1));
    *(__nv_bfloat162*)(g_xl + i + 2) =
        __floats2bfloat162_rn(v.z - __bfloat162float(h2), v.w - __bfloat162float(h3));
}

// Weights: transpose [k][n] -> [n][k] and split hi/lo
__global__ void __launch_bounds__(256) convert_w_kernel(
    const float* __restrict__ Wq, const float* __restrict__ Wk, const float* __restrict__ Wv)
{
    __shared__ float t[32][33];
    const int z = blockIdx.z;
    const float* W = (z == 0) ? Wq : (z == 1) ? Wk : Wv;
    __nv_bfloat16* oh = g_wth[z];
    __nv_bfloat16* ol = g_wtl[z];
    const int tx = threadIdx.x, ty = threadIdx.y;
    const int nb = blockIdx.x * 32, kb = blockIdx.y * 32;
#pragma unroll
    for (int i = 0; i < 32; i += 8)
        t[ty + i][tx] = W[(size_t)(kb + ty + i) * DM + nb + tx];
    __syncthreads();
#pragma unroll
    for (int i = 0; i < 32; i += 8) {
        float f = t[tx][ty + i];   // = W[kb+tx][nb+ty+i]
        __nv_bfloat16 h = __float2bfloat16(f);
        const size_t o = (size_t)(nb + ty + i) * DM + kb + tx;
        oh[o] = h;
        ol[o] = __float2bfloat16(f - __bfloat162float(h));
    }
}

// ---------------------------------------------------------------------------
// GEMM 1: QKV. A = x[8192,1024], B = W^T[1024,1024]. z = {Q,K,V}.
// ---------------------------------------------------------------------------
__global__ void __launch_bounds__(NTHREADS, 2) qkv_kernel(
    const float* __restrict__ bq, const float* __restrict__ bk, const float* __restrict__ bv)
{
    extern __shared__ __align__(1024) char smem[];
    const int z = blockIdx.z;
    const long m0 = (long)blockIdx.y * BM;
    const long n0 = (long)blockIdx.x * BN;
    float acc[4][4][4];
    run_mainloop(g_xh, g_xl, DM, m0, g_wth[z], g_wtl[z], DM, n0, DM, smem, acc);

    const float* bias = (z == 0) ? bq : (z == 1) ? bk : bv;
    const int l = threadIdx.x & 31, wid = threadIdx.x >> 5;
    const long rbase = m0 + (wid >> 2) * 64 + (l >> 2);
    const long cbase = n0 + (wid & 3) * 32 + 2 * (l & 3);

#pragma unroll
    for (int mf = 0; mf < 4; mf++)
#pragma unroll
        for (int nf = 0; nf < 4; nf++)
#pragma unroll
            for (int h = 0; h < 2; h++) {
                const long m = rbase + mf * 16 + h * 8;
                const long n = cbase + nf * 8;
                float f0 = acc[mf][nf][h * 2 + 0] + bias[n];
                float f1 = acc[mf][nf][h * 2 + 1] + bias[n + 1];
                __nv_bfloat16 h0 = __float2bfloat16(f0);
                __nv_bfloat16 h1 = __float2bfloat16(f1);
                __nv_bfloat16 l0 = __float2bfloat16(f0 - __bfloat162float(h0));
                __nv_bfloat16 l1 = __float2bfloat16(f1 - __bfloat162float(h1));
                if (z < 2) {
                    __nv_bfloat16* oh = (z == 0) ? g_qh : g_kh;
                    __nv_bfloat16* ol = (z == 0) ? g_ql : g_kl;
                    *(__nv_bfloat162*)(oh + (size_t)m * DM + n) = __halves2bfloat162(h0, h1);
                    *(__nv_bfloat162*)(ol + (size_t)m * DM + n) = __halves2bfloat162(l0, l1);
                } else {
                    const long b = m >> 11, nrow = m & (SEQ - 1);
                    const size_t o = ((size_t)b * DM + n) * SEQ + nrow;
                    g_vth[o] = h0;  g_vth[o + SEQ] = h1;
                    g_vtl[o] = l0;  g_vtl[o + SEQ] = l1;
                }
            }
}

// ---------------------------------------------------------------------------
// GEMM 2: S = scale * Q K^T per batch (fp32 out)
// ---------------------------------------------------------------------------
__global__ void __launch_bounds__(NTHREADS, 2) qk_kernel()
{
    extern __shared__ __align__(1024) char smem[];
    const int b = blockIdx.z;
    const long m0 = (long)blockIdx.y * BM;
    const long n0 = (long)blockIdx.x * BN;
    const size_t boff = (size_t)b * SEQ * DM;
    float acc[4][4][4];
    run_mainloop(g_qh + boff, g_ql + boff, DM, m0,
                 g_kh + boff, g_kl + boff, DM, n0, DM, smem, acc);

    float* sp = g_s + (size_t)b * SEQ * SEQ;
    const int l = threadIdx.x & 31, wid = threadIdx.x >> 5;
    const long rbase = m0 + (wid >> 2) * 64 + (l >> 2);
    const long cbase = n0 + (wid & 3) * 32 + 2 * (l & 3);
#pragma unroll
    for (int mf = 0; mf < 4; mf++)
#pragma unroll
        for (int nf = 0; nf < 4; nf++)
#pragma unroll
            for (int h = 0; h < 2; h++) {
                const long m = rbase + mf * 16 + h * 8;
                const long n = cbase + nf * 8;
                float2 v;
                v.x = acc[mf][nf][h * 2 + 0] * 0.03125f;
                v.y = acc[mf][nf][h * 2 + 1] * 0.03125f;
                *(float2*)(sp + (size_t)m * SEQ + n) = v;
            }
}

// ---------------------------------------------------------------------------
// Softmax rows of S -> P split hi/lo bf16
// ---------------------------------------------------------------------------
__global__ void __launch_bounds__(256) softmax_kernel()
{
    const size_t row = blockIdx.x;
    const float* p = g_s + row * (size_t)SEQ;
    __nv_bfloat16* oh = g_ph + row * (size_t)SEQ;
    __nv_bfloat16* ol = g_pl + row * (size_t)SEQ;
    const int tid = threadIdx.x;
    const int lane = tid & 31, warp = tid >> 5;
    __shared__ float red[8];

    float4 v0 = ((const float4*)p)[tid];
    float4 v1 = ((const float4*)p)[tid + 256];

    float mx = fmaxf(fmaxf(fmaxf(v0.x, v0.y), fmaxf(v0.z, v0.w)),
                     fmaxf(fmaxf(v1.x, v1.y), fmaxf(v1.z, v1.w)));
#pragma unroll
    for (int o = 16; o > 0; o >>= 1)
        mx = fmaxf(mx, __shfl_xor_sync(0xffffffffu, mx, o));
    if (lane == 0) red[warp] = mx;
    __syncthreads();
    float m = red[0];
#pragma unroll
    for (int i = 1; i < 8; i++) m = fmaxf(m, red[i]);
    __syncthreads();

    float e[8];
    e[0] = __expf(v0.x - m); e[1] = __expf(v0.y - m);
    e[2] = __expf(v0.z - m); e[3] = __expf(v0.w - m);
    e[4] = __expf(v1.x - m); e[5] = __expf(v1.y - m);
    e[6] = __expf(v1.z - m); e[7] = __expf(v1.w - m);
    float s = ((e[0] + e[1]) + (e[2] + e[3])) + ((e[4] + e[5]) + (e[6] + e[7]));
#pragma unroll
    for (int o = 16; o > 0; o >>= 1)
        s += __shfl_xor_sync(0xffffffffu, s, o);
    if (lane == 0) red[warp] = s;
    __syncthreads();
    float tot = red[0];
#pragma unroll
    for (int i = 1; i < 8; i++) tot += red[i];
    const float inv = 1.0f / tot;

#pragma unroll
    for (int j = 0; j < 2; j++) {
        const int base = (j == 0) ? tid * 4 : (tid + 256) * 4;
        float p0 = e[j * 4 + 0] * inv, p1 = e[j * 4 + 1] * inv;
        float p2 = e[j * 4 + 2] * inv, p3 = e[j * 4 + 3] * inv;
        __nv_bfloat16 h0 = __float2bfloat16(p0), h1 = __float2bfloat16(p1);
        __nv_bfloat16 h2 = __float2bfloat16(p2), h3 = __float2bfloat16(p3);
        *(__nv_bfloat162*)(oh + base)     = __halves2bfloat162(h0, h1);
        *(__nv_bfloat162*)(oh + base + 2) = __halves2bfloat162(h2, h3);
        *(__nv_bfloat162*)(ol + base) =
            __floats2bfloat162_rn(p0 - __bfloat162float(h0), p1 - __bfloat162float(h1));
        *(__nv_bfloat162*)(ol + base + 2) =
            __floats2bfloat162_rn(p2 - __bfloat162float(h2), p3 - __bfloat162float(h3));
    }
}

// ---------------------------------------------------------------------------
// GEMM 3: O = P V per batch. A = P[2048,2048], B = V^T[1024,2048]. fp32 out.
// ---------------------------------------------------------------------------
__global__ void __launch_bounds__(NTHREADS, 2) pv_kernel(float* __restrict__ out)
{
    extern __shared__ __align__(1024) char smem[];
    const int b = blockIdx.z;
    const long m0 = (long)blockIdx.y * BM;
    const long n0 = (long)blockIdx.x * BN;
    const size_t poff = (size_t)b * SEQ * SEQ;
    const size_t voff = (size_t)b * DM * SEQ;
    float acc[4][4][4];
    run_mainloop(g_ph + poff, g_pl + poff, SEQ, m0,
                 g_vth + voff, g_vtl + voff, SEQ, n0, SEQ, smem, acc);

    float* op = out + (size_t)b * SEQ * DM;
    const int l = threadIdx.x & 31, wid = threadIdx.x >> 5;
    const long rbase = m0 + (wid >> 2) * 64 + (l >> 2);
    const long cbase = n0 + (wid & 3) * 32 + 2 * (l & 3);
#pragma unroll
    for (int mf = 0; mf < 4; mf++)
#pragma unroll
        for (int nf = 0; nf < 4; nf++)
#pragma unroll
            for (int h = 0; h < 2; h++) {
                const long m = rbase + mf * 16 + h * 8;
                const long n = cbase + nf * 8;
                float2 v;
                v.x = acc[mf][nf][h * 2 + 0];
                v.y = acc[mf][nf][h * 2 + 1];
                *(float2*)(op + (size_t)m * DM + n) = v;
            }
}

// ---------------------------------------------------------------------------
extern "C" void kernel_launch(void* const* d_in, const int* in_sizes, int n_in,
                              void* d_out, int out_size)
{
    (void)in_sizes; (void)n_in; (void)out_size;
    const float* x  = (const float*)d_in[0];
    const float* Wq = (const float*)d_in[1];
    const float* Wk = (const float*)d_in[2];
    const float* Wv = (const float*)d_in[3];
    const float* bq = (const float*)d_in[4];
    const float* bk = (const float*)d_in[5];
    const float* bv = (const float*)d_in[6];
    float* out = (float*)d_out;

    cudaFuncSetAttribute(qkv_kernel, cudaFuncAttributeMaxDynamicSharedMemorySize, SMEM_TOTAL);
    cudaFuncSetAttribute(qk_kernel,  cudaFuncAttributeMaxDynamicSharedMemorySize, SMEM_TOTAL);
    cudaFuncSetAttribute(pv_kernel,  cudaFuncAttributeMaxDynamicSharedMemorySize, SMEM_TOTAL);

    convert_x_kernel<<<(TOKENS * DM) / (256 * 4), 256>>>(x);
    convert_w_kernel<<<dim3(DM / 32, DM / 32, 3), dim3(32, 8)>>>(Wq, Wk, Wv);
    qkv_kernel<<<dim3(DM / BN, TOKENS / BM, 3), NTHREADS, SMEM_TOTAL>>>(bq, bk, bv);
    qk_kernel<<<dim3(SEQ / BN, SEQ / BM, BATCH), NTHREADS, SMEM_TOTAL>>>();
    softmax_kernel<<<BATCH * SEQ, 256>>>();
    pv_kernel<<<dim3(DM / BN, SEQ / BM, BATCH), NTHREADS, SMEM_TOTAL>>>(out);
}